// round 1
// baseline (speedup 1.0000x reference)
#include <cuda_runtime.h>
#include <math.h>

#define BB   8
#define NT   512
#define NC   2048
#define EMB  512
#define H    8
#define DK   64
#define DV   64
#define EPSV 1e-6f

#define OUT_ELEMS ((size_t)BB * NT * EMB)            // 2,097,152
#define NQVEC (BB * H * NT)                          // 32768
#define NKVEC (BB * H * NC)                          // 131072

// ---------------- scratch (static device globals; no runtime alloc) ----------
__device__ float g_q [BB * H * NT * DK];   // 8 MB   [b][h][t][d]
__device__ float g_k [BB * H * NC * DK];   // 32 MB  [b][h][c][d]
__device__ float g_v [BB * H * NC * DV];   // 32 MB  [b][h][c][d]
__device__ float g_qn [NQVEC];
__device__ float g_qnr[NQVEC];
__device__ float g_kn [NKVEC];
__device__ float g_knr[NKVEC];
__device__ float g_ho[BB * NT * H * DV];   // 8 MB   [b][t][h][d]

// ---------------- generic NT GEMM: C = A(MxK) * B(NxK)^T + bias --------------
// MODE 0: C[m*N+n] plain.  MODE 1: head-scatter to [(b*H+h)*ntok + t]*64 + d.
template <int MODE>
__global__ __launch_bounds__(256) void gemm_nt_kernel(
    const float* __restrict__ A, const float* __restrict__ Bm,
    const float* __restrict__ bias, float* __restrict__ C,
    int M, int N, int K, int ntok)
{
    __shared__ float As[16][128];
    __shared__ float Bs[16][128];
    const int tid = threadIdx.x;
    const int tx = tid & 15, ty = tid >> 4;
    const int row0 = blockIdx.y * 128, col0 = blockIdx.x * 128;

    float acc[8][8];
#pragma unroll
    for (int i = 0; i < 8; i++)
#pragma unroll
        for (int j = 0; j < 8; j++) acc[i][j] = 0.f;

    for (int k0 = 0; k0 < K; k0 += 16) {
#pragma unroll
        for (int i = 0; i < 2; i++) {
            int idx = tid + i * 256;           // 0..511
            int r   = idx >> 2;                // 0..127
            int c4  = (idx & 3) << 2;          // 0,4,8,12
            float4 va = *(const float4*)(A  + (size_t)(row0 + r) * K + k0 + c4);
            As[c4 + 0][r] = va.x; As[c4 + 1][r] = va.y;
            As[c4 + 2][r] = va.z; As[c4 + 3][r] = va.w;
            float4 vb = *(const float4*)(Bm + (size_t)(col0 + r) * K + k0 + c4);
            Bs[c4 + 0][r] = vb.x; Bs[c4 + 1][r] = vb.y;
            Bs[c4 + 2][r] = vb.z; Bs[c4 + 3][r] = vb.w;
        }
        __syncthreads();
#pragma unroll
        for (int kk = 0; kk < 16; kk++) {
            float a[8], b[8];
            *(float4*)&a[0] = *(const float4*)&As[kk][ty * 8];
            *(float4*)&a[4] = *(const float4*)&As[kk][ty * 8 + 4];
            *(float4*)&b[0] = *(const float4*)&Bs[kk][tx * 8];
            *(float4*)&b[4] = *(const float4*)&Bs[kk][tx * 8 + 4];
#pragma unroll
            for (int i = 0; i < 8; i++)
#pragma unroll
                for (int j = 0; j < 8; j++)
                    acc[i][j] = fmaf(a[i], b[j], acc[i][j]);
        }
        __syncthreads();
    }

#pragma unroll
    for (int i = 0; i < 8; i++) {
        int m = row0 + ty * 8 + i;
        int bb = 0, t = 0;
        if (MODE == 1) { bb = m / ntok; t = m - bb * ntok; }
#pragma unroll
        for (int j = 0; j < 8; j++) {
            int n = col0 + tx * 8 + j;
            float val = acc[i][j] + bias[n];
            if (MODE == 0) {
                C[(size_t)m * N + n] = val;
            } else {
                int h = n >> 6, d = n & 63;
                C[(((size_t)(bb * H + h)) * ntok + t) * 64 + d] = val;
            }
        }
    }
}

// ---------------- per-vector L2 norms + reciprocals (warp per vector) --------
__global__ void norms_kernel(const float* __restrict__ q, const float* __restrict__ k)
{
    int w    = (blockIdx.x * blockDim.x + threadIdx.x) >> 5;
    int lane = threadIdx.x & 31;
    if (w >= NQVEC + NKVEC) return;
    const float* base = (w < NQVEC) ? (q + (size_t)w * 64)
                                    : (k + (size_t)(w - NQVEC) * 64);
    float2 t = ((const float2*)base)[lane];
    float s = t.x * t.x + t.y * t.y;
#pragma unroll
    for (int o = 16; o; o >>= 1) s += __shfl_xor_sync(0xffffffffu, s, o);
    if (lane == 0) {
        float nrm = sqrtf(s);
        float r   = (nrm > 0.f) ? 1.0f / nrm : 0.f;
        if (w < NQVEC) { g_qn[w] = nrm; g_qnr[w] = r; }
        else           { g_kn[w - NQVEC] = nrm; g_knr[w - NQVEC] = r; }
    }
}

// ---------------- logits: att = (q . k) / max(|q||k|, eps) -------------------
__global__ __launch_bounds__(256) void logits_kernel(float* __restrict__ att)
{
    __shared__ float As[16][128];
    __shared__ float Bs[16][128];
    const int bh = blockIdx.z;
    const float* A  = g_q + (size_t)bh * NT * DK;
    const float* Bm = g_k + (size_t)bh * NC * DK;
    const int row0 = blockIdx.y * 128, col0 = blockIdx.x * 128;
    const int tid = threadIdx.x;
    const int tx = tid & 15, ty = tid >> 4;

    float acc[8][8];
#pragma unroll
    for (int i = 0; i < 8; i++)
#pragma unroll
        for (int j = 0; j < 8; j++) acc[i][j] = 0.f;

    for (int k0 = 0; k0 < DK; k0 += 16) {
#pragma unroll
        for (int i = 0; i < 2; i++) {
            int idx = tid + i * 256;
            int r   = idx >> 2;
            int c4  = (idx & 3) << 2;
            float4 va = *(const float4*)(A  + (size_t)(row0 + r) * DK + k0 + c4);
            As[c4 + 0][r] = va.x; As[c4 + 1][r] = va.y;
            As[c4 + 2][r] = va.z; As[c4 + 3][r] = va.w;
            float4 vb = *(const float4*)(Bm + (size_t)(col0 + r) * DK + k0 + c4);
            Bs[c4 + 0][r] = vb.x; Bs[c4 + 1][r] = vb.y;
            Bs[c4 + 2][r] = vb.z; Bs[c4 + 3][r] = vb.w;
        }
        __syncthreads();
#pragma unroll
        for (int kk = 0; kk < 16; kk++) {
            float a[8], b[8];
            *(float4*)&a[0] = *(const float4*)&As[kk][ty * 8];
            *(float4*)&a[4] = *(const float4*)&As[kk][ty * 8 + 4];
            *(float4*)&b[0] = *(const float4*)&Bs[kk][tx * 8];
            *(float4*)&b[4] = *(const float4*)&Bs[kk][tx * 8 + 4];
#pragma unroll
            for (int i = 0; i < 8; i++)
#pragma unroll
                for (int j = 0; j < 8; j++)
                    acc[i][j] = fmaf(a[i], b[j], acc[i][j]);
        }
        __syncthreads();
    }

    float qv[8], rq[8], kv[8], rk[8];
#pragma unroll
    for (int i = 0; i < 8; i++) {
        int m = row0 + ty * 8 + i;
        qv[i] = g_qn [bh * NT + m];
        rq[i] = g_qnr[bh * NT + m];
    }
#pragma unroll
    for (int j = 0; j < 8; j++) {
        int n = col0 + tx * 8 + j;
        kv[j] = g_kn [bh * NC + n];
        rk[j] = g_knr[bh * NC + n];
    }
#pragma unroll
    for (int i = 0; i < 8; i++) {
        int m = row0 + ty * 8 + i;
        size_t rowbase = ((size_t)(bh * NT + m)) * NC;
#pragma unroll
        for (int j = 0; j < 8; j++) {
            int n = col0 + tx * 8 + j;
            float prod = qv[i] * kv[j];
            float inv  = (prod > EPSV) ? (rq[i] * rk[j]) : (1.0f / EPSV);
            att[rowbase + n] = acc[i][j] * inv;
        }
    }
}

// ---------------- FFMA-only exp (avoid MUFU: 33.5M exps) ---------------------
__device__ __forceinline__ float fast_exp(float x)
{
    float t  = x * 1.4426950408889634f;
    float kf = rintf(t);
    float r  = fmaf(kf, -0.6931471805599453f, x);
    float p  = fmaf(r, 0.0083333333f, 0.041666667f);
    p = fmaf(r, p, 0.16666667f);
    p = fmaf(r, p, 0.5f);
    p = fmaf(r, p, 1.0f);
    p = fmaf(r, p, 1.0f);
    int ki = (int)kf;
    float s = __int_as_float((ki + 127) << 23);
    return p * s;
}

// ---------------- softmax over last dim (2048), in place ---------------------
__global__ __launch_bounds__(256) void softmax_kernel(float* __restrict__ att)
{
    __shared__ float red[256];
    const int row = blockIdx.x;
    float* p = att + (size_t)row * NC;
    const int tid = threadIdx.x;

    float4 v0 = ((const float4*)p)[tid];
    float4 v1 = ((const float4*)p)[tid + 256];

    float mx = fmaxf(fmaxf(fmaxf(v0.x, v0.y), fmaxf(v0.z, v0.w)),
                     fmaxf(fmaxf(v1.x, v1.y), fmaxf(v1.z, v1.w)));
    red[tid] = mx; __syncthreads();
#pragma unroll
    for (int s = 128; s > 0; s >>= 1) {
        if (tid < s) red[tid] = fmaxf(red[tid], red[tid + s]);
        __syncthreads();
    }
    float m = red[0];
    __syncthreads();

    v0.x = fast_exp(v0.x - m); v0.y = fast_exp(v0.y - m);
    v0.z = fast_exp(v0.z - m); v0.w = fast_exp(v0.w - m);
    v1.x = fast_exp(v1.x - m); v1.y = fast_exp(v1.y - m);
    v1.z = fast_exp(v1.z - m); v1.w = fast_exp(v1.w - m);

    float sum = (v0.x + v0.y + v0.z + v0.w) + (v1.x + v1.y + v1.z + v1.w);
    red[tid] = sum; __syncthreads();
#pragma unroll
    for (int s = 128; s > 0; s >>= 1) {
        if (tid < s) red[tid] += red[tid + s];
        __syncthreads();
    }
    if (tid == 0) red[0] = 1.0f / red[0];
    __syncthreads();
    float inv = red[0];

    v0.x *= inv; v0.y *= inv; v0.z *= inv; v0.w *= inv;
    v1.x *= inv; v1.y *= inv; v1.z *= inv; v1.w *= inv;
    ((float4*)p)[tid]       = v0;
    ((float4*)p)[tid + 256] = v1;
}

// ---------------- out_head = att @ v  (per b,h; NN GEMM 512x64x2048) ---------
__global__ __launch_bounds__(256) void av_kernel(const float* __restrict__ att)
{
    __shared__ float As[128][33];
    __shared__ float Bs[32][64];
    const int bh = blockIdx.y;
    const int b  = bh >> 3, h = bh & 7;
    const int row0 = blockIdx.x * 128;
    const float* Ap = att + (size_t)bh * NT * NC + (size_t)row0 * NC;
    const float* Bp = g_v + (size_t)bh * NC * DV;
    const int tid = threadIdx.x;
    const int tx = tid & 15, ty = tid >> 4;   // cols: tx*4+j (64), rows: ty*8+i (128)

    float acc[8][4];
#pragma unroll
    for (int i = 0; i < 8; i++)
#pragma unroll
        for (int j = 0; j < 4; j++) acc[i][j] = 0.f;

    for (int k0 = 0; k0 < NC; k0 += 32) {
#pragma unroll
        for (int i = 0; i < 4; i++) {
            int idx = tid + i * 256;          // 0..1023
            int r   = idx >> 3;               // 0..127
            int c4  = (idx & 7) << 2;         // 0..28
            float4 va = *(const float4*)(Ap + (size_t)r * NC + k0 + c4);
            As[r][c4 + 0] = va.x; As[r][c4 + 1] = va.y;
            As[r][c4 + 2] = va.z; As[r][c4 + 3] = va.w;
        }
#pragma unroll
        for (int i = 0; i < 2; i++) {
            int idx = tid + i * 256;          // 0..511
            int r   = idx >> 4;               // 0..31
            int c4  = (idx & 15) << 2;        // 0..60
            *(float4*)&Bs[r][c4] = *(const float4*)(Bp + (size_t)(k0 + r) * DV + c4);
        }
        __syncthreads();
#pragma unroll
        for (int kk = 0; kk < 32; kk++) {
            float4 bv = *(const float4*)&Bs[kk][tx * 4];
            float a[8];
#pragma unroll
            for (int i = 0; i < 8; i++) a[i] = As[ty * 8 + i][kk];
#pragma unroll
            for (int i = 0; i < 8; i++) {
                acc[i][0] = fmaf(a[i], bv.x, acc[i][0]);
                acc[i][1] = fmaf(a[i], bv.y, acc[i][1]);
                acc[i][2] = fmaf(a[i], bv.z, acc[i][2]);
                acc[i][3] = fmaf(a[i], bv.w, acc[i][3]);
            }
        }
        __syncthreads();
    }

#pragma unroll
    for (int i = 0; i < 8; i++) {
        int t = row0 + ty * 8 + i;
        size_t base = (((size_t)b * NT + t) * H + h) * DV + tx * 4;
        float4 o = make_float4(acc[i][0], acc[i][1], acc[i][2], acc[i][3]);
        *(float4*)&g_ho[base] = o;
    }
}

// ---------------- launch ----------------------------------------------------
extern "C" void kernel_launch(void* const* d_in, const int* in_sizes, int n_in,
                              void* d_out, int out_size)
{
    const float* queries = (const float*)d_in[0];
    const float* keys    = (const float*)d_in[1];
    const float* values  = (const float*)d_in[2];
    const float* W_At    = (const float*)d_in[3];
    const float* b_At    = (const float*)d_in[4];
    const float* W_Ac    = (const float*)d_in[5];
    const float* b_Ac    = (const float*)d_in[6];
    const float* W_Bc    = (const float*)d_in[7];
    const float* b_Bc    = (const float*)d_in[8];
    const float* W_R     = (const float*)d_in[9];
    const float* b_R     = (const float*)d_in[10];

    float* out = (float*)d_out;
    float* att = out + OUT_ELEMS;

    float *q, *k, *v;
    cudaGetSymbolAddress((void**)&q, g_q);
    cudaGetSymbolAddress((void**)&k, g_k);
    cudaGetSymbolAddress((void**)&v, g_v);
    float* ho;
    cudaGetSymbolAddress((void**)&ho, g_ho);

    // projections -> head layouts
    gemm_nt_kernel<1><<<dim3(4, 32),  256>>>(queries, W_At, b_At, q, BB * NT, H * DK, EMB, NT);
    gemm_nt_kernel<1><<<dim3(4, 128), 256>>>(keys,    W_Ac, b_Ac, k, BB * NC, H * DK, EMB, NC);
    gemm_nt_kernel<1><<<dim3(4, 128), 256>>>(values,  W_Bc, b_Bc, v, BB * NC, H * DV, EMB, NC);

    // norms + reciprocals
    norms_kernel<<<(NQVEC + NKVEC) / 8, 256>>>(q, k);

    // cosine logits
    logits_kernel<<<dim3(NC / 128, NT / 128, BB * H), 256>>>(att);

    // softmax in place
    softmax_kernel<<<BB * H * NT, 256>>>(att);

    // att @ v -> head outputs in [b][t][h][d]
    av_kernel<<<dim3(NT / 128, BB * H), 256>>>(att);

    // final projection
    gemm_nt_kernel<0><<<dim3(4, 32), 256>>>(ho, W_R, b_R, out, BB * NT, EMB, H * DV, 0);
}

// round 3
// speedup vs baseline: 3.4238x; 3.4238x over previous
#include <cuda_runtime.h>
#include <math.h>
#include <stdint.h>

#define B_   8
#define NTOK 512
#define NCTX 2048
#define EMBD 512
#define HH   8
#define DKV  64
#define EPSV 1e-6f

#define OUT_ELEMS ((size_t)B_ * NTOK * EMBD)
#define NQVEC (B_ * HH * NTOK)
#define NKVEC (B_ * HH * NCTX)

// ---------------- scratch ----------------------------------------------------
__device__ float g_q [B_ * HH * NTOK * DKV];   // [bh][t][d]
__device__ float g_k [B_ * HH * NCTX * DKV];   // [bh][c][d]
__device__ float g_v [B_ * HH * NCTX * DKV];   // [bh][c][d]
__device__ float g_qn [NQVEC];
__device__ float g_qnr[NQVEC];
__device__ float g_kn [NKVEC];
__device__ float g_knr[NKVEC];
__device__ float g_ho [B_ * NTOK * HH * DKV];  // [b][t][h][d]

// ---------------- helpers ----------------------------------------------------
__device__ __forceinline__ uint32_t f2tf(float x) {
    uint32_t r; asm("cvt.rna.tf32.f32 %0, %1;" : "=r"(r) : "f"(x)); return r;
}
__device__ __forceinline__ void mma8(float* c, const uint32_t* a, const uint32_t* b) {
    asm volatile(
        "mma.sync.aligned.m16n8k8.row.col.f32.tf32.tf32.f32 "
        "{%0,%1,%2,%3}, {%4,%5,%6,%7}, {%8,%9}, {%0,%1,%2,%3};"
        : "+f"(c[0]), "+f"(c[1]), "+f"(c[2]), "+f"(c[3])
        : "r"(a[0]), "r"(a[1]), "r"(a[2]), "r"(a[3]), "r"(b[0]), "r"(b[1]));
}

// ---------------- unified mma.sync tf32 GEMM ---------------------------------
// D[m][n] = sum_k A[m][k] * B[n][k]   (NT: B K-major)  or  B[k][n] (NN, BNN=true)
// MODE 0: C[m*N+n] = acc + bias[n]
// MODE 1: proj scatter: C[((b*H+h)*ntok + t)*64 + d] = acc + bias[n]
// MODE 3: logits (z=bh): C = att, value = acc * cosine reciprocal
// MODE 4: AV (z=bh):     C = ho,  C[((b*NTOK+t)*H+h)*64 + n] = acc
template <int BN, bool BNN, int MODE>
__global__ __launch_bounds__(256) void gemm_mma(
    const float* __restrict__ A, const float* __restrict__ Bm,
    const float* __restrict__ bias, float* __restrict__ C,
    int M, int N, int K, int ntok)
{
    constexpr int BM = 128;
    constexpr int NTILES  = BN / 16;            // per-warp n tiles (warp covers BN/2)
    constexpr int ASTR = 20;                    // row stride (floats), conflict-free
    constexpr int BSTR = BNN ? (BN + 8) : 20;
    constexpr int ABUF = BM * ASTR;
    constexpr int BBUF = BNN ? 16 * BSTR : BN * 20;

    __shared__ float As[2][ABUF];
    __shared__ float Bs[2][BBUF];

    const int tid  = threadIdx.x;
    const int wid  = tid >> 5;
    const int lane = tid & 31;
    const int r    = lane >> 2;      // group id
    const int cq   = lane & 3;       // thread-in-group
    const int wm   = wid & 3;        // 4 warps down M (32 rows each)
    const int wn   = wid >> 2;       // 2 warps across N (BN/2 cols each)

    const int row0 = blockIdx.y * BM;
    const int col0 = blockIdx.x * BN;
    const int bh   = blockIdx.z;

    const float* Ap = A;
    const float* Bp = Bm;
    if (MODE == 3) { Ap = A + (size_t)bh * NTOK * DKV;  Bp = Bm + (size_t)bh * NCTX * DKV; }
    if (MODE == 4) { Ap = A + (size_t)bh * NTOK * NCTX; Bp = Bm + (size_t)bh * NCTX * DKV; }

    // -------- slab loader: LDG fp32 -> cvt.rna tf32 -> STS --------------------
    auto load_slab = [&](int buf, int k0) {
        // A: BM x 16, row-major stride 20
#pragma unroll
        for (int it = 0; it < 2; it++) {
            int row = (tid >> 2) + it * 64;
            int k4  = (tid & 3) * 4;
            float4 v = *(const float4*)(Ap + (size_t)(row0 + row) * K + k0 + k4);
            float* d = &As[buf][row * ASTR + k4];
            d[0] = __uint_as_float(f2tf(v.x)); d[1] = __uint_as_float(f2tf(v.y));
            d[2] = __uint_as_float(f2tf(v.z)); d[3] = __uint_as_float(f2tf(v.w));
        }
        if (!BNN) {
            // B: BN x 16, row-major stride 20
#pragma unroll
            for (int it = 0; it < BN / 64; it++) {
                int row = (tid >> 2) + it * 64;
                int k4  = (tid & 3) * 4;
                float4 v = *(const float4*)(Bp + (size_t)(col0 + row) * K + k0 + k4);
                float* d = &Bs[buf][row * BSTR + k4];
                d[0] = __uint_as_float(f2tf(v.x)); d[1] = __uint_as_float(f2tf(v.y));
                d[2] = __uint_as_float(f2tf(v.z)); d[3] = __uint_as_float(f2tf(v.w));
            }
        } else {
            // B: 16 x BN (k-major rows), BN == 64
            int krow = tid >> 4;
            int n4   = (tid & 15) * 4;
            float4 v = *(const float4*)(Bp + (size_t)(k0 + krow) * N + col0 + n4);
            float* d = &Bs[buf][krow * BSTR + n4];
            d[0] = __uint_as_float(f2tf(v.x)); d[1] = __uint_as_float(f2tf(v.y));
            d[2] = __uint_as_float(f2tf(v.z)); d[3] = __uint_as_float(f2tf(v.w));
        }
    };

    float cr[2][NTILES][4];
#pragma unroll
    for (int mt = 0; mt < 2; mt++)
#pragma unroll
        for (int nt = 0; nt < NTILES; nt++)
#pragma unroll
            for (int e = 0; e < 4; e++) cr[mt][nt][e] = 0.f;

    const int S = K >> 4;
    load_slab(0, 0);
    __syncthreads();

    for (int s = 0; s < S; s++) {
        if (s + 1 < S) load_slab((s + 1) & 1, (s + 1) * 16);
        const int buf = s & 1;
#pragma unroll
        for (int ks = 0; ks < 2; ks++) {
            uint32_t af[2][4];
#pragma unroll
            for (int mt = 0; mt < 2; mt++) {
                int mrow = wm * 32 + mt * 16 + r;
                af[mt][0] = __float_as_uint(As[buf][ mrow      * ASTR + ks * 8 + cq    ]);
                af[mt][1] = __float_as_uint(As[buf][(mrow + 8) * ASTR + ks * 8 + cq    ]);
                af[mt][2] = __float_as_uint(As[buf][ mrow      * ASTR + ks * 8 + cq + 4]);
                af[mt][3] = __float_as_uint(As[buf][(mrow + 8) * ASTR + ks * 8 + cq + 4]);
            }
            uint32_t bf[NTILES][2];
#pragma unroll
            for (int nt = 0; nt < NTILES; nt++) {
                if (!BNN) {
                    int nrow = wn * (BN / 2) + nt * 8 + r;
                    bf[nt][0] = __float_as_uint(Bs[buf][nrow * BSTR + ks * 8 + cq    ]);
                    bf[nt][1] = __float_as_uint(Bs[buf][nrow * BSTR + ks * 8 + cq + 4]);
                } else {
                    int ncol = wn * (BN / 2) + nt * 8 + r;
                    bf[nt][0] = __float_as_uint(Bs[buf][(ks * 8 + cq    ) * BSTR + ncol]);
                    bf[nt][1] = __float_as_uint(Bs[buf][(ks * 8 + cq + 4) * BSTR + ncol]);
                }
            }
#pragma unroll
            for (int mt = 0; mt < 2; mt++)
#pragma unroll
                for (int nt = 0; nt < NTILES; nt++)
                    mma8(cr[mt][nt], af[mt], bf[nt]);
        }
        __syncthreads();
    }

    // -------- epilogue --------------------------------------------------------
#pragma unroll
    for (int mt = 0; mt < 2; mt++) {
        const int m1 = row0 + wm * 32 + mt * 16 + r;
        const int m2 = m1 + 8;

        float qv1, rq1, qv2, rq2;
        if (MODE == 3) {
            qv1 = g_qn[bh * NTOK + m1]; rq1 = g_qnr[bh * NTOK + m1];
            qv2 = g_qn[bh * NTOK + m2]; rq2 = g_qnr[bh * NTOK + m2];
        }

#pragma unroll
        for (int nt = 0; nt < NTILES; nt++) {
            const int n = col0 + wn * (BN / 2) + nt * 8 + 2 * cq;
            const float* cc = cr[mt][nt];

            if constexpr (MODE == 0) {
                float bx = bias[n], by = bias[n + 1];
                *(float2*)(C + (size_t)m1 * N + n) = make_float2(cc[0] + bx, cc[1] + by);
                *(float2*)(C + (size_t)m2 * N + n) = make_float2(cc[2] + bx, cc[3] + by);
            } else if constexpr (MODE == 1) {
                float bx = bias[n], by = bias[n + 1];
                int h = n >> 6, d0 = n & 63;
                int b1v = m1 / ntok, t1 = m1 - b1v * ntok;
                int b2v = m2 / ntok, t2 = m2 - b2v * ntok;
                *(float2*)(C + (((size_t)(b1v * HH + h)) * ntok + t1) * 64 + d0) =
                    make_float2(cc[0] + bx, cc[1] + by);
                *(float2*)(C + (((size_t)(b2v * HH + h)) * ntok + t2) * 64 + d0) =
                    make_float2(cc[2] + bx, cc[3] + by);
            } else if constexpr (MODE == 3) {
                float2 knv = *(const float2*)&g_kn [bh * NCTX + n];
                float2 krv = *(const float2*)&g_knr[bh * NCTX + n];
                float i1x = (qv1 * knv.x > EPSV) ? rq1 * krv.x : 1e6f;
                float i1y = (qv1 * knv.y > EPSV) ? rq1 * krv.y : 1e6f;
                float i2x = (qv2 * knv.x > EPSV) ? rq2 * krv.x : 1e6f;
                float i2y = (qv2 * knv.y > EPSV) ? rq2 * krv.y : 1e6f;
                *(float2*)(C + ((size_t)(bh * NTOK + m1)) * NCTX + n) =
                    make_float2(cc[0] * i1x, cc[1] * i1y);
                *(float2*)(C + ((size_t)(bh * NTOK + m2)) * NCTX + n) =
                    make_float2(cc[2] * i2x, cc[3] * i2y);
            } else { // MODE 4
                int b = bh >> 3, h = bh & 7;
                *(float2*)(C + (((size_t)(b * NTOK + m1)) * HH + h) * 64 + n) =
                    make_float2(cc[0], cc[1]);
                *(float2*)(C + (((size_t)(b * NTOK + m2)) * HH + h) * 64 + n) =
                    make_float2(cc[2], cc[3]);
            }
        }
    }
}

// ---------------- per-vector L2 norms + reciprocals --------------------------
__global__ void norms_kernel(const float* __restrict__ q, const float* __restrict__ k)
{
    int w    = (blockIdx.x * blockDim.x + threadIdx.x) >> 5;
    int lane = threadIdx.x & 31;
    if (w >= NQVEC + NKVEC) return;
    const float* base = (w < NQVEC) ? (q + (size_t)w * 64) : (k + (size_t)(w - NQVEC) * 64);
    float2 t = ((const float2*)base)[lane];
    float s = t.x * t.x + t.y * t.y;
#pragma unroll
    for (int o = 16; o; o >>= 1) s += __shfl_xor_sync(0xffffffffu, s, o);
    if (lane == 0) {
        float nrm = sqrtf(s);
        float rv  = (nrm > 0.f) ? 1.0f / nrm : 0.f;
        if (w < NQVEC) { g_qn[w] = nrm; g_qnr[w] = rv; }
        else           { g_kn[w - NQVEC] = nrm; g_knr[w - NQVEC] = rv; }
    }
}

// ---------------- FFMA-only exp ----------------------------------------------
__device__ __forceinline__ float fast_exp(float x)
{
    float t  = x * 1.4426950408889634f;
    float kf = rintf(t);
    float rr = fmaf(kf, -0.6931471805599453f, x);
    float p  = fmaf(rr, 0.0083333333f, 0.041666667f);
    p = fmaf(rr, p, 0.16666667f);
    p = fmaf(rr, p, 0.5f);
    p = fmaf(rr, p, 1.0f);
    p = fmaf(rr, p, 1.0f);
    return p * __int_as_float(((int)kf + 127) << 23);
}

// ---------------- softmax over last dim (2048), in place ---------------------
__global__ __launch_bounds__(256) void softmax_kernel(float* __restrict__ att)
{
    __shared__ float red[256];
    const int row = blockIdx.x;
    float* p = att + (size_t)row * NCTX;
    const int tid = threadIdx.x;

    float4 v0 = ((const float4*)p)[tid];
    float4 v1 = ((const float4*)p)[tid + 256];

    float mx = fmaxf(fmaxf(fmaxf(v0.x, v0.y), fmaxf(v0.z, v0.w)),
                     fmaxf(fmaxf(v1.x, v1.y), fmaxf(v1.z, v1.w)));
    red[tid] = mx; __syncthreads();
#pragma unroll
    for (int s = 128; s > 0; s >>= 1) {
        if (tid < s) red[tid] = fmaxf(red[tid], red[tid + s]);
        __syncthreads();
    }
    float m = red[0];
    __syncthreads();

    v0.x = fast_exp(v0.x - m); v0.y = fast_exp(v0.y - m);
    v0.z = fast_exp(v0.z - m); v0.w = fast_exp(v0.w - m);
    v1.x = fast_exp(v1.x - m); v1.y = fast_exp(v1.y - m);
    v1.z = fast_exp(v1.z - m); v1.w = fast_exp(v1.w - m);

    float sum = (v0.x + v0.y + v0.z + v0.w) + (v1.x + v1.y + v1.z + v1.w);
    red[tid] = sum; __syncthreads();
#pragma unroll
    for (int s = 128; s > 0; s >>= 1) {
        if (tid < s) red[tid] += red[tid + s];
        __syncthreads();
    }
    if (tid == 0) red[0] = 1.0f / red[0];
    __syncthreads();
    float inv = red[0];

    v0.x *= inv; v0.y *= inv; v0.z *= inv; v0.w *= inv;
    v1.x *= inv; v1.y *= inv; v1.z *= inv; v1.w *= inv;
    ((float4*)p)[tid]       = v0;
    ((float4*)p)[tid + 256] = v1;
}

// ---------------- launch -----------------------------------------------------
extern "C" void kernel_launch(void* const* d_in, const int* in_sizes, int n_in,
                              void* d_out, int out_size)
{
    const float* queries = (const float*)d_in[0];
    const float* keys    = (const float*)d_in[1];
    const float* values  = (const float*)d_in[2];
    const float* W_At    = (const float*)d_in[3];
    const float* b_At    = (const float*)d_in[4];
    const float* W_Ac    = (const float*)d_in[5];
    const float* b_Ac    = (const float*)d_in[6];
    const float* W_Bc    = (const float*)d_in[7];
    const float* b_Bc    = (const float*)d_in[8];
    const float* W_R     = (const float*)d_in[9];
    const float* b_R     = (const float*)d_in[10];

    float* out = (float*)d_out;
    float* att = out + OUT_ELEMS;

    float *q, *k, *v, *ho;
    cudaGetSymbolAddress((void**)&q,  g_q);
    cudaGetSymbolAddress((void**)&k,  g_k);
    cudaGetSymbolAddress((void**)&v,  g_v);
    cudaGetSymbolAddress((void**)&ho, g_ho);

    // projections (head-scatter epilogue)
    gemm_mma<128, false, 1><<<dim3(4, 32),  256>>>(queries, W_At, b_At, q, B_ * NTOK, HH * DKV, EMBD, NTOK);
    gemm_mma<128, false, 1><<<dim3(4, 128), 256>>>(keys,    W_Ac, b_Ac, k, B_ * NCTX, HH * DKV, EMBD, NCTX);
    gemm_mma<128, false, 1><<<dim3(4, 128), 256>>>(values,  W_Bc, b_Bc, v, B_ * NCTX, HH * DKV, EMBD, NCTX);

    // norms + reciprocals
    norms_kernel<<<(NQVEC + NKVEC) / 8, 256>>>(q, k);

    // cosine logits
    gemm_mma<128, false, 3><<<dim3(16, 4, B_ * HH), 256>>>(q, k, nullptr, att, NTOK, NCTX, DKV, 0);

    // softmax in place
    softmax_kernel<<<B_ * HH * NTOK, 256>>>(att);

    // att @ V  (NN: V read [c][d] directly)
    gemm_mma<64, true, 4><<<dim3(1, 4, B_ * HH), 256>>>(att, v, nullptr, ho, NTOK, DKV, NCTX, 0);

    // output projection
    gemm_mma<128, false, 0><<<dim3(4, 32), 256>>>(ho, W_R, b_R, out, B_ * NTOK, EMBD, HH * DKV, 0);
}